// round 1
// baseline (speedup 1.0000x reference)
#include <cuda_runtime.h>

// GCBFSafetyLayer: the reference's QP projection uses A = L_g_h = zeros,
// so the per-constraint update gate (nrm > 1e-6) is always false and the
// solver returns u0 = raw_action unchanged. Output == raw_action exactly.
//
// Inputs (metadata order): positions, velocities, obstacles, raw_action.
// Output: safe_action (B*N*D = 8192 float32) = raw_action.

__global__ void copy_raw_action_kernel(const float4* __restrict__ src,
                                       float4* __restrict__ dst,
                                       int n_vec4) {
    int i = blockIdx.x * blockDim.x + threadIdx.x;
    if (i < n_vec4) {
        dst[i] = src[i];
    }
}

__global__ void copy_raw_action_tail(const float* __restrict__ src,
                                     float* __restrict__ dst,
                                     int start, int n) {
    int i = start + blockIdx.x * blockDim.x + threadIdx.x;
    if (i < n) {
        dst[i] = src[i];
    }
}

extern "C" void kernel_launch(void* const* d_in, const int* in_sizes, int n_in,
                              void* d_out, int out_size) {
    const float* raw_action = (const float*)d_in[3];
    float* out = (float*)d_out;

    int n = out_size;           // 8192 expected
    int n_vec4 = n / 4;         // 2048 float4s

    if (n_vec4 > 0) {
        int threads = 256;
        int blocks = (n_vec4 + threads - 1) / threads;
        copy_raw_action_kernel<<<blocks, threads>>>(
            (const float4*)raw_action, (float4*)out, n_vec4);
    }
    int tail_start = n_vec4 * 4;
    if (tail_start < n) {
        int rem = n - tail_start;
        copy_raw_action_tail<<<1, 32>>>(raw_action, out, tail_start, n);
        (void)rem;
    }
}